// round 1
// baseline (speedup 1.0000x reference)
#include <cuda_runtime.h>

#define NODES   4096
#define PAIRS   (NODES / 2)
#define THREADS 512

// Per-output-node map: {src0, src1, float_bits(a), float_bits(b)}
// out[row][n] = a * row[src0] + b * row[src1]
__device__ int4 g_map[NODES];

__global__ void setup_kernel(const float* __restrict__ angles,
                             const int* __restrict__ pairs,
                             const int* __restrict__ outp_pairs) {
    int p = blockIdx.x * blockDim.x + threadIdx.x;
    if (p < PAIRS) {
        float s, c;
        sincosf(angles[p], &s, &c);
        int a0 = pairs[2 * p];
        int a1 = pairs[2 * p + 1];
        int o0 = outp_pairs[2 * p];
        int o1 = outp_pairs[2 * p + 1];
        // yi = c*x[a0] - s*x[a1]  -> out[o0]
        // yj = c*x[a1] + s*x[a0]  -> out[o1]
        g_map[o0] = make_int4(a0, a1, __float_as_int(c), __float_as_int(-s));
        g_map[o1] = make_int4(a1, a0, __float_as_int(c), __float_as_int(s));
    }
}

__global__ void __launch_bounds__(THREADS, 1)
rot_kernel(const float* __restrict__ inp, float* __restrict__ outp) {
    __shared__ float row[NODES];

    const int tid = threadIdx.x;
    const size_t base = (size_t)blockIdx.x * NODES;

    // Coalesced load of the full row into shared memory (float4)
    const float4* in4 = (const float4*)(inp + base);
    float4* srow = (float4*)row;
#pragma unroll
    for (int i = 0; i < NODES / 4 / THREADS; i++)
        srow[tid + i * THREADS] = in4[tid + i * THREADS];

    __syncthreads();

    float4* out4 = (float4*)(outp + base);
#pragma unroll
    for (int i = 0; i < NODES / 4 / THREADS; i++) {
        int q = tid + i * THREADS;   // float4 index within row
        int n = q * 4;               // node index
        float4 v;
        int4 m;
        m = g_map[n + 0];
        v.x = __int_as_float(m.z) * row[m.x] + __int_as_float(m.w) * row[m.y];
        m = g_map[n + 1];
        v.y = __int_as_float(m.z) * row[m.x] + __int_as_float(m.w) * row[m.y];
        m = g_map[n + 2];
        v.z = __int_as_float(m.z) * row[m.x] + __int_as_float(m.w) * row[m.y];
        m = g_map[n + 3];
        v.w = __int_as_float(m.z) * row[m.x] + __int_as_float(m.w) * row[m.y];
        out4[q] = v;   // coalesced STG.128
    }
}

extern "C" void kernel_launch(void* const* d_in, const int* in_sizes, int n_in,
                              void* d_out, int out_size) {
    const float* inp        = (const float*)d_in[0];
    const float* angles     = (const float*)d_in[1];
    const int*   pairs      = (const int*)d_in[2];
    const int*   outp_pairs = (const int*)d_in[3];
    float*       outp       = (float*)d_out;

    int rows = in_sizes[0] / NODES;   // 8 * 1024 = 8192

    setup_kernel<<<(PAIRS + 1023) / 1024, 1024>>>(angles, pairs, outp_pairs);
    rot_kernel<<<rows, THREADS>>>(inp, outp);
}

// round 2
// speedup vs baseline: 1.9207x; 1.9207x over previous
#include <cuda_runtime.h>

#define NODES   4096
#define PAIRS   (NODES / 2)
#define THREADS 512
#define R       4            // rows per block

// Per-output-node map: {src0, src1, float_bits(a), float_bits(b)}
// out[row][n] = a * row[src0] + b * row[src1]
__device__ int4 g_map[NODES];

__global__ void setup_kernel(const float* __restrict__ angles,
                             const int* __restrict__ pairs,
                             const int* __restrict__ outp_pairs) {
    int p = blockIdx.x * blockDim.x + threadIdx.x;
    if (p < PAIRS) {
        float s, c;
        sincosf(angles[p], &s, &c);
        int a0 = pairs[2 * p];
        int a1 = pairs[2 * p + 1];
        int o0 = outp_pairs[2 * p];
        int o1 = outp_pairs[2 * p + 1];
        g_map[o0] = make_int4(a0, a1, __float_as_int(c), __float_as_int(-s));
        g_map[o1] = make_int4(a1, a0, __float_as_int(c), __float_as_int(s));
    }
}

// Dynamic smem: float4 s[NODES]; s[n] holds rows r0..r0+3 at node n (64 KB).
extern __shared__ float4 s_tile[];

__global__ void __launch_bounds__(THREADS)
rot_kernel(const float* __restrict__ inp, float* __restrict__ outp) {
    const int tid = threadIdx.x;
    const size_t base = (size_t)blockIdx.x * R * NODES;

    const float* r0 = inp + base;
    const float* r1 = r0 + NODES;
    const float* r2 = r1 + NODES;
    const float* r3 = r2 + NODES;

    // Stage: transpose 4 rows into [node][row] records.
    // Per iteration: 4 coalesced LDG.32 + 1 sequential STS.128 (conflict-free).
#pragma unroll
    for (int i = 0; i < NODES / THREADS; i++) {
        int n = tid + i * THREADS;
        float4 v;
        v.x = r0[n];
        v.y = r1[n];
        v.z = r2[n];
        v.w = r3[n];
        s_tile[n] = v;
    }
    __syncthreads();

    float* o0 = outp + base;
    float* o1 = o0 + NODES;
    float* o2 = o1 + NODES;
    float* o3 = o2 + NODES;

    // Gather: one map entry + two LDS.128 produce 4 rows of output node n.
#pragma unroll 4
    for (int i = 0; i < NODES / THREADS; i++) {
        int n = tid + i * THREADS;
        int4 m = g_map[n];
        float a = __int_as_float(m.z);
        float b = __int_as_float(m.w);
        float4 x = s_tile[m.x];
        float4 y = s_tile[m.y];
        o0[n] = a * x.x + b * y.x;
        o1[n] = a * x.y + b * y.y;
        o2[n] = a * x.z + b * y.z;
        o3[n] = a * x.w + b * y.w;
    }
}

extern "C" void kernel_launch(void* const* d_in, const int* in_sizes, int n_in,
                              void* d_out, int out_size) {
    const float* inp        = (const float*)d_in[0];
    const float* angles     = (const float*)d_in[1];
    const int*   pairs      = (const int*)d_in[2];
    const int*   outp_pairs = (const int*)d_in[3];
    float*       outp       = (float*)d_out;

    int rows = in_sizes[0] / NODES;           // 8192
    int smem = NODES * sizeof(float4);        // 64 KB

    static bool attr_set = false;
    if (!attr_set) {
        cudaFuncSetAttribute(rot_kernel,
                             cudaFuncAttributeMaxDynamicSharedMemorySize, smem);
        attr_set = true;
    }

    setup_kernel<<<(PAIRS + 1023) / 1024, 1024>>>(angles, pairs, outp_pairs);
    rot_kernel<<<rows / R, THREADS, smem>>>(inp, outp);
}